// round 15
// baseline (speedup 1.0000x reference)
#include <cuda_runtime.h>
#include <cuda_fp16.h>
#include <cstdint>

// Problem constants (fixed by the reference)
#define BB   8
#define KK   100000
#define CC   16
#define OO   16
#define HH   512
#define WW   512
#define NNODES (BB * KK)          // 800000
#define NPIX_B (HH * WW)          // 262144
#define ALPHA_PRIOR 1.0f

#define GROUPS  (NNODES / 16)     // 50000 groups of 16 nodes
#define GITER   5                 // groups per warp
#define TBLK    256               // 8 warps
#define TGRID   (GROUPS / (GITER * (TBLK / 32)))      // 1250 blocks
#define GRID_U4 ((size_t)2 * BB * NPIX_B)             // 4,194,304 uint4

// Scratch grid: fp16 half-planar [half][batch][H*W], 4 x half2 = 8 ch = 16B per
// pixel-half. 67 MB. The zero pass both clears it AND re-warms it into L2
// before scatter's atomics (critical: measured in R14's regression).
__device__ uint4 g_grid[2][BB][NPIX_B];

// ---------------------------------------------------------------------------
// Kernel 0: zero the grid (grid-stride, full-chip). Doubles as L2 prefetch.
// ---------------------------------------------------------------------------
__global__ __launch_bounds__(256) void zero_kernel() {
    const uint4 z = make_uint4(0u, 0u, 0u, 0u);
    uint4* gz = (uint4*)g_grid;
    size_t stride = (size_t)gridDim.x * 256;
    for (size_t i = (size_t)blockIdx.x * 256 + threadIdx.x; i < GRID_U4; i += stride)
        gz[i] = z;
}

// ---------------------------------------------------------------------------
// Helpers
// ---------------------------------------------------------------------------
__device__ __forceinline__ unsigned f2h2(float a, float b) {
    __half2 h = __floats2half2_rn(a, b);
    return *reinterpret_cast<unsigned*>(&h);
}

__device__ __forceinline__ void mma16816(float d[4],
                                         const unsigned a[4],
                                         const unsigned b0, const unsigned b1) {
    asm volatile(
        "mma.sync.aligned.m16n8k16.row.col.f32.f16.f16.f32 "
        "{%0,%1,%2,%3}, {%4,%5,%6,%7}, {%8,%9}, {%10,%11,%12,%13};"
        : "=f"(d[0]), "=f"(d[1]), "=f"(d[2]), "=f"(d[3])
        : "r"(a[0]), "r"(a[1]), "r"(a[2]), "r"(a[3]),
          "r"(b0), "r"(b1),
          "f"(0.f), "f"(0.f), "f"(0.f), "f"(0.f));
}

// ---------------------------------------------------------------------------
// Kernel 1: scatter — tensor-core transform fused with grid atomics.
// Warp step: 16 nodes; 4x HMMA; shfl-down gather; 8 lanes issue
// red.global.add.noftz.v4.f16x2 (proven R13 config).
// ---------------------------------------------------------------------------
__global__ __launch_bounds__(TBLK) void scatter_kernel(
    const float* __restrict__ node_feat,   // [B,K,C]
    const float* __restrict__ node_xy,     // [B,K,2]
    const int*   __restrict__ node_types,  // [B,K]
    const float* __restrict__ w_obj,       // [O,C]
    const float* __restrict__ w_prior)     // [O,C]
{
    int lane = threadIdx.x & 31;
    int wid  = threadIdx.x >> 5;
    int g    = lane >> 2;                  // 0..7  (mma groupID)
    int t    = lane & 3;                   // 0..3  (thread-in-group)

    const float2* wo2 = (const float2*)w_obj;
    const float2* wp2 = (const float2*)w_prior;
    float2 f;
    unsigned bo_lo0, bo_lo1, bo_hi0, bo_hi1, bp_lo0, bp_lo1, bp_hi0, bp_hi1;
    f = __ldg(&wo2[g * 8 + t]);           bo_lo0 = f2h2(f.x, f.y);
    f = __ldg(&wo2[g * 8 + 4 + t]);       bo_lo1 = f2h2(f.x, f.y);
    f = __ldg(&wo2[(g + 8) * 8 + t]);     bo_hi0 = f2h2(f.x, f.y);
    f = __ldg(&wo2[(g + 8) * 8 + 4 + t]); bo_hi1 = f2h2(f.x, f.y);
    f = __ldg(&wp2[g * 8 + t]);           bp_lo0 = f2h2(ALPHA_PRIOR * f.x, ALPHA_PRIOR * f.y);
    f = __ldg(&wp2[g * 8 + 4 + t]);       bp_lo1 = f2h2(ALPHA_PRIOR * f.x, ALPHA_PRIOR * f.y);
    f = __ldg(&wp2[(g + 8) * 8 + t]);     bp_hi0 = f2h2(ALPHA_PRIOR * f.x, ALPHA_PRIOR * f.y);
    f = __ldg(&wp2[(g + 8) * 8 + 4 + t]); bp_hi1 = f2h2(ALPHA_PRIOR * f.x, ALPHA_PRIOR * f.y);

    const float2* f2p = (const float2*)node_feat;   // f2p[n*8 + c/2]
    const float2* xyp = (const float2*)node_xy;

    int warp_global = blockIdx.x * (TBLK / 32) + wid;

    for (int it = 0; it < GITER; it++) {
        int base = (warp_global * GITER + it) * 16;
        int n0 = base + g;
        int n1 = base + g + 8;

        unsigned a[4];
        f = __ldg(&f2p[(size_t)n0 * 8 + t]);     a[0] = f2h2(f.x, f.y);
        f = __ldg(&f2p[(size_t)n1 * 8 + t]);     a[1] = f2h2(f.x, f.y);
        f = __ldg(&f2p[(size_t)n0 * 8 + 4 + t]); a[2] = f2h2(f.x, f.y);
        f = __ldg(&f2p[(size_t)n1 * 8 + 4 + t]); a[3] = f2h2(f.x, f.y);

        float dol[4], doh[4], dpl[4], dph[4];
        mma16816(dol, a, bo_lo0, bo_lo1);
        mma16816(doh, a, bo_hi0, bo_hi1);
        mma16816(dpl, a, bp_lo0, bp_lo1);
        mma16816(dph, a, bp_hi0, bp_hi1);

        int t0 = __ldg(&node_types[n0]) & 1;
        int t1 = __ldg(&node_types[n1]) & 1;
        unsigned hlo0 = f2h2(t0 ? dpl[0] : dol[0], t0 ? dpl[1] : dol[1]);
        unsigned hhi0 = f2h2(t0 ? dph[0] : doh[0], t0 ? dph[1] : doh[1]);
        unsigned hlo1 = f2h2(t1 ? dpl[2] : dol[2], t1 ? dpl[3] : dol[3]);
        unsigned hhi1 = f2h2(t1 ? dph[2] : doh[2], t1 ? dph[3] : doh[3]);

        unsigned lo0_1 = __shfl_down_sync(0xffffffffu, hlo0, 1);
        unsigned lo0_2 = __shfl_down_sync(0xffffffffu, hlo0, 2);
        unsigned lo0_3 = __shfl_down_sync(0xffffffffu, hlo0, 3);
        unsigned hi0_1 = __shfl_down_sync(0xffffffffu, hhi0, 1);
        unsigned hi0_2 = __shfl_down_sync(0xffffffffu, hhi0, 2);
        unsigned hi0_3 = __shfl_down_sync(0xffffffffu, hhi0, 3);
        unsigned lo1_1 = __shfl_down_sync(0xffffffffu, hlo1, 1);
        unsigned lo1_2 = __shfl_down_sync(0xffffffffu, hlo1, 2);
        unsigned lo1_3 = __shfl_down_sync(0xffffffffu, hlo1, 3);
        unsigned hi1_1 = __shfl_down_sync(0xffffffffu, hhi1, 1);
        unsigned hi1_2 = __shfl_down_sync(0xffffffffu, hhi1, 2);
        unsigned hi1_3 = __shfl_down_sync(0xffffffffu, hhi1, 3);

        if (t == 0) {
            float2 xy0 = __ldg(&xyp[n0]);
            float2 xy1 = __ldg(&xyp[n1]);
            // jnp.round == round-half-to-even == rintf; clip to [0, 511]
            int ix0 = (int)fminf(fmaxf(rintf(xy0.x), 0.f), (float)(WW - 1));
            int iy0 = (int)fminf(fmaxf(rintf(xy0.y), 0.f), (float)(HH - 1));
            int ix1 = (int)fminf(fmaxf(rintf(xy1.x), 0.f), (float)(WW - 1));
            int iy1 = (int)fminf(fmaxf(rintf(xy1.y), 0.f), (float)(HH - 1));
            int b0 = n0 / KK, b1 = n1 / KK;
            uint4* p00 = &g_grid[0][b0][iy0 * WW + ix0];
            uint4* p01 = &g_grid[1][b0][iy0 * WW + ix0];
            uint4* p10 = &g_grid[0][b1][iy1 * WW + ix1];
            uint4* p11 = &g_grid[1][b1][iy1 * WW + ix1];
            asm volatile("red.global.add.noftz.v4.f16x2 [%0], {%1, %2, %3, %4};"
                         :: "l"(p00), "r"(hlo0), "r"(lo0_1), "r"(lo0_2), "r"(lo0_3)
                         : "memory");
            asm volatile("red.global.add.noftz.v4.f16x2 [%0], {%1, %2, %3, %4};"
                         :: "l"(p01), "r"(hhi0), "r"(hi0_1), "r"(hi0_2), "r"(hi0_3)
                         : "memory");
            asm volatile("red.global.add.noftz.v4.f16x2 [%0], {%1, %2, %3, %4};"
                         :: "l"(p10), "r"(hlo1), "r"(lo1_1), "r"(lo1_2), "r"(lo1_3)
                         : "memory");
            asm volatile("red.global.add.noftz.v4.f16x2 [%0], {%1, %2, %3, %4};"
                         :: "l"(p11), "r"(hhi1), "r"(hi1_1), "r"(hi1_2), "r"(hi1_3)
                         : "memory");
        }
    }
}

// ---------------------------------------------------------------------------
// Kernel 2: conv — depthwise 3x3 over fp16 half-planes, 8-row strips (10 rows
// read / 8 produced), fp32 math, NCHW fp32 writeout (streaming stores).
// Thread: one x, one channel-half (8 ch). Grid = (8, 64, 8) = 4096 blocks.
// ---------------------------------------------------------------------------
__global__ __launch_bounds__(128) void conv_kernel(float* __restrict__ out) {
    int lane = threadIdx.x & 31;
    int w    = threadIdx.x >> 5;               // 0..3
    int h    = w & 1;                          // channel-half
    int x    = blockIdx.x * 64 + (w >> 1) * 32 + lane;  // 0..511
    int y0   = blockIdx.y * 8;                 // strip start
    int b    = blockIdx.z;

    const uint4* plane = g_grid[h][b];
    const uint4 z16 = make_uint4(0u, 0u, 0u, 0u);

    float acc[8][8];
    #pragma unroll
    for (int j = 0; j < 8; j++)
        #pragma unroll
        for (int i = 0; i < 8; i++) acc[j][i] = 0.f;

    #pragma unroll
    for (int r = 0; r < 10; r++) {
        int yy = y0 - 1 + r;
        if ((unsigned)yy >= HH) continue;      // y zero-pad

        const uint4* row = plane + (size_t)yy * WW;
        uint4 cq = __ldg(row + x);
        uint4 lq = (x > 0)      ? __ldg(row + x - 1) : z16;
        uint4 rq = (x < WW - 1) ? __ldg(row + x + 1) : z16;

        const __half2* ch = (const __half2*)&cq;
        const __half2* lh = (const __half2*)&lq;
        const __half2* rh = (const __half2*)&rq;

        float u[8], v[8];
        #pragma unroll
        for (int j = 0; j < 4; j++) {
            float2 cf = __half22float2(ch[j]);
            float2 lf = __half22float2(lh[j]);
            float2 rf = __half22float2(rh[j]);
            float sx = lf.x + rf.x, sy = lf.y + rf.y;
            u[2*j+0] = 0.075f * sx + 0.125f * cf.x;
            u[2*j+1] = 0.075f * sy + 0.125f * cf.y;
            v[2*j+0] = 0.125f * sx + 0.300f * cf.x;
            v[2*j+1] = 0.125f * sy + 0.300f * cf.y;
        }

        #pragma unroll
        for (int j = 0; j < 8; j++) {
            int d = (r - 1) - j;               // input row offset from output row
            if (d == 0) {
                #pragma unroll
                for (int i = 0; i < 8; i++) acc[j][i] += v[i];
            } else if (d == 1 || d == -1) {
                #pragma unroll
                for (int i = 0; i < 8; i++) acc[j][i] += u[i];
            }
        }
    }

    // NCHW writeout: channels o = 8h..8h+7. Warp-coalesced streaming stores.
    const size_t plane_out = (size_t)HH * WW;
    size_t base = ((size_t)b * OO + h * 8) * plane_out + (size_t)y0 * WW + x;
    #pragma unroll
    for (int i = 0; i < 8; i++)
        #pragma unroll
        for (int j = 0; j < 8; j++)
            __stcs(&out[base + (size_t)i * plane_out + (size_t)j * WW], acc[j][i]);
}

// ---------------------------------------------------------------------------
// Launch: zero(+L2 warm) -> fused scatter -> conv. 3 launches, one stream.
// Inputs: node_feat, node_xy, hw(int64, unused), node_types, w_obj, w_prior.
// ---------------------------------------------------------------------------
extern "C" void kernel_launch(void* const* d_in, const int* in_sizes, int n_in,
                              void* d_out, int out_size) {
    const float* node_feat  = (const float*)d_in[0];
    const float* node_xy    = (const float*)d_in[1];
    const int*   node_types = (const int*)d_in[3];
    const float* w_obj      = (const float*)d_in[4];
    const float* w_prior    = (const float*)d_in[5];
    float* out = (float*)d_out;

    zero_kernel<<<4096, 256>>>();                      // 67 MB, 4 uint4/thread
    scatter_kernel<<<TGRID, TBLK>>>(node_feat, node_xy, node_types,
                                    w_obj, w_prior);
    dim3 conv_grid(WW / 64, HH / 8, BB);               // (8, 64, 8)
    conv_kernel<<<conv_grid, 128>>>(out);
}

// round 16
// speedup vs baseline: 1.2092x; 1.2092x over previous
#include <cuda_runtime.h>
#include <cuda_fp16.h>
#include <cstdint>

// Problem constants (fixed by the reference)
#define BB   8
#define KK   100000
#define CC   16
#define OO   16
#define HH   512
#define WW   512
#define NNODES (BB * KK)          // 800000
#define NPIX_B (HH * WW)          // 262144
#define ALPHA_PRIOR 1.0f

#define GROUPS  (NNODES / 16)     // 50000 groups of 16 nodes
#define GITER   5                 // groups per warp
#define TBLK    256               // 8 warps
#define TGRID   (GROUPS / (GITER * (TBLK / 32)))      // 1250 blocks
#define GRID_U4 ((size_t)2 * BB * NPIX_B)             // 4,194,304 uint4

// Scratch grid: fp16 half-planar [half][batch][H*W], 4 x half2 = 8 ch = 16B per
// pixel-half. 67 MB. The zero pass both clears it AND re-warms it into L2
// before scatter's atomics (R14 regression proved this matters).
__device__ uint4 g_grid[2][BB][NPIX_B];

// ---------------------------------------------------------------------------
// Kernel 0: zero the grid (grid-stride, full-chip). Doubles as L2 prefetch.
// ---------------------------------------------------------------------------
__global__ __launch_bounds__(256) void zero_kernel() {
    const uint4 z = make_uint4(0u, 0u, 0u, 0u);
    uint4* gz = (uint4*)g_grid;
    size_t stride = (size_t)gridDim.x * 256;
    for (size_t i = (size_t)blockIdx.x * 256 + threadIdx.x; i < GRID_U4; i += stride)
        gz[i] = z;
}

// ---------------------------------------------------------------------------
// Helpers
// ---------------------------------------------------------------------------
__device__ __forceinline__ unsigned f2h2(float a, float b) {
    __half2 h = __floats2half2_rn(a, b);
    return *reinterpret_cast<unsigned*>(&h);
}

__device__ __forceinline__ void mma16816(float d[4],
                                         const unsigned a[4],
                                         const unsigned b0, const unsigned b1) {
    asm volatile(
        "mma.sync.aligned.m16n8k16.row.col.f32.f16.f16.f32 "
        "{%0,%1,%2,%3}, {%4,%5,%6,%7}, {%8,%9}, {%10,%11,%12,%13};"
        : "=f"(d[0]), "=f"(d[1]), "=f"(d[2]), "=f"(d[3])
        : "r"(a[0]), "r"(a[1]), "r"(a[2]), "r"(a[3]),
          "r"(b0), "r"(b1),
          "f"(0.f), "f"(0.f), "f"(0.f), "f"(0.f));
}

// ---------------------------------------------------------------------------
// Kernel 1: scatter — tensor-core transform fused with grid atomics
// (byte-identical to the proven R13 version).
// ---------------------------------------------------------------------------
__global__ __launch_bounds__(TBLK) void scatter_kernel(
    const float* __restrict__ node_feat,   // [B,K,C]
    const float* __restrict__ node_xy,     // [B,K,2]
    const int*   __restrict__ node_types,  // [B,K]
    const float* __restrict__ w_obj,       // [O,C]
    const float* __restrict__ w_prior)     // [O,C]
{
    int lane = threadIdx.x & 31;
    int wid  = threadIdx.x >> 5;
    int g    = lane >> 2;                  // 0..7  (mma groupID)
    int t    = lane & 3;                   // 0..3  (thread-in-group)

    const float2* wo2 = (const float2*)w_obj;
    const float2* wp2 = (const float2*)w_prior;
    float2 f;
    unsigned bo_lo0, bo_lo1, bo_hi0, bo_hi1, bp_lo0, bp_lo1, bp_hi0, bp_hi1;
    f = __ldg(&wo2[g * 8 + t]);           bo_lo0 = f2h2(f.x, f.y);
    f = __ldg(&wo2[g * 8 + 4 + t]);       bo_lo1 = f2h2(f.x, f.y);
    f = __ldg(&wo2[(g + 8) * 8 + t]);     bo_hi0 = f2h2(f.x, f.y);
    f = __ldg(&wo2[(g + 8) * 8 + 4 + t]); bo_hi1 = f2h2(f.x, f.y);
    f = __ldg(&wp2[g * 8 + t]);           bp_lo0 = f2h2(ALPHA_PRIOR * f.x, ALPHA_PRIOR * f.y);
    f = __ldg(&wp2[g * 8 + 4 + t]);       bp_lo1 = f2h2(ALPHA_PRIOR * f.x, ALPHA_PRIOR * f.y);
    f = __ldg(&wp2[(g + 8) * 8 + t]);     bp_hi0 = f2h2(ALPHA_PRIOR * f.x, ALPHA_PRIOR * f.y);
    f = __ldg(&wp2[(g + 8) * 8 + 4 + t]); bp_hi1 = f2h2(ALPHA_PRIOR * f.x, ALPHA_PRIOR * f.y);

    const float2* f2p = (const float2*)node_feat;   // f2p[n*8 + c/2]
    const float2* xyp = (const float2*)node_xy;

    int warp_global = blockIdx.x * (TBLK / 32) + wid;

    for (int it = 0; it < GITER; it++) {
        int base = (warp_global * GITER + it) * 16;
        int n0 = base + g;
        int n1 = base + g + 8;

        unsigned a[4];
        f = __ldg(&f2p[(size_t)n0 * 8 + t]);     a[0] = f2h2(f.x, f.y);
        f = __ldg(&f2p[(size_t)n1 * 8 + t]);     a[1] = f2h2(f.x, f.y);
        f = __ldg(&f2p[(size_t)n0 * 8 + 4 + t]); a[2] = f2h2(f.x, f.y);
        f = __ldg(&f2p[(size_t)n1 * 8 + 4 + t]); a[3] = f2h2(f.x, f.y);

        float dol[4], doh[4], dpl[4], dph[4];
        mma16816(dol, a, bo_lo0, bo_lo1);
        mma16816(doh, a, bo_hi0, bo_hi1);
        mma16816(dpl, a, bp_lo0, bp_lo1);
        mma16816(dph, a, bp_hi0, bp_hi1);

        int t0 = __ldg(&node_types[n0]) & 1;
        int t1 = __ldg(&node_types[n1]) & 1;
        unsigned hlo0 = f2h2(t0 ? dpl[0] : dol[0], t0 ? dpl[1] : dol[1]);
        unsigned hhi0 = f2h2(t0 ? dph[0] : doh[0], t0 ? dph[1] : doh[1]);
        unsigned hlo1 = f2h2(t1 ? dpl[2] : dol[2], t1 ? dpl[3] : dol[3]);
        unsigned hhi1 = f2h2(t1 ? dph[2] : doh[2], t1 ? dph[3] : doh[3]);

        unsigned lo0_1 = __shfl_down_sync(0xffffffffu, hlo0, 1);
        unsigned lo0_2 = __shfl_down_sync(0xffffffffu, hlo0, 2);
        unsigned lo0_3 = __shfl_down_sync(0xffffffffu, hlo0, 3);
        unsigned hi0_1 = __shfl_down_sync(0xffffffffu, hhi0, 1);
        unsigned hi0_2 = __shfl_down_sync(0xffffffffu, hhi0, 2);
        unsigned hi0_3 = __shfl_down_sync(0xffffffffu, hhi0, 3);
        unsigned lo1_1 = __shfl_down_sync(0xffffffffu, hlo1, 1);
        unsigned lo1_2 = __shfl_down_sync(0xffffffffu, hlo1, 2);
        unsigned lo1_3 = __shfl_down_sync(0xffffffffu, hlo1, 3);
        unsigned hi1_1 = __shfl_down_sync(0xffffffffu, hhi1, 1);
        unsigned hi1_2 = __shfl_down_sync(0xffffffffu, hhi1, 2);
        unsigned hi1_3 = __shfl_down_sync(0xffffffffu, hhi1, 3);

        if (t == 0) {
            float2 xy0 = __ldg(&xyp[n0]);
            float2 xy1 = __ldg(&xyp[n1]);
            // jnp.round == round-half-to-even == rintf; clip to [0, 511]
            int ix0 = (int)fminf(fmaxf(rintf(xy0.x), 0.f), (float)(WW - 1));
            int iy0 = (int)fminf(fmaxf(rintf(xy0.y), 0.f), (float)(HH - 1));
            int ix1 = (int)fminf(fmaxf(rintf(xy1.x), 0.f), (float)(WW - 1));
            int iy1 = (int)fminf(fmaxf(rintf(xy1.y), 0.f), (float)(HH - 1));
            int b0 = n0 / KK, b1 = n1 / KK;
            uint4* p00 = &g_grid[0][b0][iy0 * WW + ix0];
            uint4* p01 = &g_grid[1][b0][iy0 * WW + ix0];
            uint4* p10 = &g_grid[0][b1][iy1 * WW + ix1];
            uint4* p11 = &g_grid[1][b1][iy1 * WW + ix1];
            asm volatile("red.global.add.noftz.v4.f16x2 [%0], {%1, %2, %3, %4};"
                         :: "l"(p00), "r"(hlo0), "r"(lo0_1), "r"(lo0_2), "r"(lo0_3)
                         : "memory");
            asm volatile("red.global.add.noftz.v4.f16x2 [%0], {%1, %2, %3, %4};"
                         :: "l"(p01), "r"(hhi0), "r"(hi0_1), "r"(hi0_2), "r"(hi0_3)
                         : "memory");
            asm volatile("red.global.add.noftz.v4.f16x2 [%0], {%1, %2, %3, %4};"
                         :: "l"(p10), "r"(hlo1), "r"(lo1_1), "r"(lo1_2), "r"(lo1_3)
                         : "memory");
            asm volatile("red.global.add.noftz.v4.f16x2 [%0], {%1, %2, %3, %4};"
                         :: "l"(p11), "r"(hhi1), "r"(hi1_1), "r"(hi1_2), "r"(hi1_3)
                         : "memory");
        }
    }
}

// ---------------------------------------------------------------------------
// Kernel 2: conv — depthwise 3x3 over fp16 half-planes, 4-row strips (R13
// shape), but u/v partials AND 3-row accumulation in __half2 (2 ch/instr);
// fp32 conversion only at the final store. Grid = (8, 128, 8), 128 threads.
// ---------------------------------------------------------------------------
__global__ __launch_bounds__(128) void conv_kernel(float* __restrict__ out) {
    int lane = threadIdx.x & 31;
    int w    = threadIdx.x >> 5;               // 0..3
    int h    = w & 1;                          // channel-half
    int x    = blockIdx.x * 64 + (w >> 1) * 32 + lane;  // 0..511
    int y0   = blockIdx.y * 4;                 // strip start
    int b    = blockIdx.z;

    const uint4* plane = g_grid[h][b];
    const uint4 z16 = make_uint4(0u, 0u, 0u, 0u);

    const __half2 k075 = __floats2half2_rn(0.075f, 0.075f);
    const __half2 k125 = __floats2half2_rn(0.125f, 0.125f);
    const __half2 k300 = __floats2half2_rn(0.300f, 0.300f);
    const __half2 hz   = __floats2half2_rn(0.f, 0.f);

    __half2 acc[4][4];                          // [row][ch-pair]
    #pragma unroll
    for (int j = 0; j < 4; j++)
        #pragma unroll
        for (int i = 0; i < 4; i++) acc[j][i] = hz;

    #pragma unroll
    for (int r = 0; r < 6; r++) {
        int yy = y0 - 1 + r;
        if ((unsigned)yy >= HH) continue;      // y zero-pad

        const uint4* row = plane + (size_t)yy * WW;
        uint4 cq = __ldg(row + x);
        uint4 lq = (x > 0)      ? __ldg(row + x - 1) : z16;
        uint4 rq = (x < WW - 1) ? __ldg(row + x + 1) : z16;

        const __half2* ch = (const __half2*)&cq;
        const __half2* lh = (const __half2*)&lq;
        const __half2* rh = (const __half2*)&rq;

        __half2 u[4], v[4];
        #pragma unroll
        for (int i = 0; i < 4; i++) {
            __half2 s = __hadd2(lh[i], rh[i]);
            u[i] = __hfma2(s, k075, __hmul2(ch[i], k125));
            v[i] = __hfma2(s, k125, __hmul2(ch[i], k300));
        }

        #pragma unroll
        for (int j = 0; j < 4; j++) {
            int d = (r - 1) - j;               // input row offset from output row
            if (d == 0) {
                #pragma unroll
                for (int i = 0; i < 4; i++) acc[j][i] = __hadd2(acc[j][i], v[i]);
            } else if (d == 1 || d == -1) {
                #pragma unroll
                for (int i = 0; i < 4; i++) acc[j][i] = __hadd2(acc[j][i], u[i]);
            }
        }
    }

    // NCHW writeout: channels o = 8h..8h+7, fp32 conversion at the store.
    const size_t plane_out = (size_t)HH * WW;
    size_t base = ((size_t)b * OO + h * 8) * plane_out + (size_t)y0 * WW + x;
    #pragma unroll
    for (int i = 0; i < 4; i++)
        #pragma unroll
        for (int j = 0; j < 4; j++) {
            float2 fv = __half22float2(acc[j][i]);
            __stcs(&out[base + (size_t)(2 * i)     * plane_out + (size_t)j * WW], fv.x);
            __stcs(&out[base + (size_t)(2 * i + 1) * plane_out + (size_t)j * WW], fv.y);
        }
}

// ---------------------------------------------------------------------------
// Launch: zero(+L2 warm) -> fused scatter -> conv. 3 launches, one stream.
// Inputs: node_feat, node_xy, hw(int64, unused), node_types, w_obj, w_prior.
// ---------------------------------------------------------------------------
extern "C" void kernel_launch(void* const* d_in, const int* in_sizes, int n_in,
                              void* d_out, int out_size) {
    const float* node_feat  = (const float*)d_in[0];
    const float* node_xy    = (const float*)d_in[1];
    const int*   node_types = (const int*)d_in[3];
    const float* w_obj      = (const float*)d_in[4];
    const float* w_prior    = (const float*)d_in[5];
    float* out = (float*)d_out;

    zero_kernel<<<4096, 256>>>();                      // 67 MB, 4 uint4/thread
    scatter_kernel<<<TGRID, TBLK>>>(node_feat, node_xy, node_types,
                                    w_obj, w_prior);
    dim3 conv_grid(WW / 64, HH / 4, BB);               // (8, 128, 8)
    conv_kernel<<<conv_grid, 128>>>(out);
}